// round 4
// baseline (speedup 1.0000x reference)
#include <cuda_runtime.h>
#include <cuda_fp16.h>
#include <cstdint>

#define DIM 128
#define TM  64   // rows per CTA

// ---------------------------------------------------------------------------
// Global scratch (no allocations allowed)
// ---------------------------------------------------------------------------
__device__ __align__(16) __half g_Bc[DIM * DIM];   // Mc = Wo@Wv, fp16, row-major [n][k]
__device__ unsigned char g_mask[131072];

__device__ __forceinline__ uint32_t smem_u32(const void* p) {
    uint32_t a;
    asm("{ .reg .u64 t; cvta.to.shared.u64 t, %1; cvt.u32.u64 %0, t; }" : "=r"(a) : "l"(p));
    return a;
}
__device__ __forceinline__ void ldsm4(uint32_t& r0, uint32_t& r1, uint32_t& r2,
                                      uint32_t& r3, uint32_t a) {
    asm volatile("ldmatrix.sync.aligned.m8n8.x4.shared.b16 {%0,%1,%2,%3}, [%4];"
                 : "=r"(r0), "=r"(r1), "=r"(r2), "=r"(r3) : "r"(a));
}
__device__ __forceinline__ void mma16816(float* c, const uint32_t* a, const uint32_t* b) {
    asm volatile(
        "mma.sync.aligned.m16n8k16.row.col.f32.f16.f16.f32 "
        "{%0,%1,%2,%3},{%4,%5,%6,%7},{%8,%9},{%0,%1,%2,%3};"
        : "+f"(c[0]), "+f"(c[1]), "+f"(c[2]), "+f"(c[3])
        : "r"(a[0]), "r"(a[1]), "r"(a[2]), "r"(a[3]), "r"(b[0]), "r"(b[1]));
}
__device__ __forceinline__ void cp_async16(uint32_t dst, const void* src) {
    asm volatile("cp.async.ca.shared.global [%0], [%1], 16;" :: "r"(dst), "l"(src)
                 : "memory");
}

// ---------------------------------------------------------------------------
// Kernel 1: Mc = Wo @ Wv -> fp16, 4-way k-split per output; clear mask.
// ---------------------------------------------------------------------------
__global__ void prep_kernel(const float* __restrict__ Wo,
                            const float* __restrict__ Wv, int N) {
    __shared__ float WoS[DIM];
    const int b = blockIdx.x;
    const int i = b >> 2;
    const int jb = (b & 3) * 32;
    const int tid = threadIdx.x;
    WoS[tid] = Wo[i * DIM + tid];
    __syncthreads();

    const int j = jb + (tid >> 2);
    const int kl = tid & 3;
    float a0 = 0.f, a1 = 0.f, a2 = 0.f, a3 = 0.f;
#pragma unroll
    for (int kk = 0; kk < 32; kk += 4) {
        int k = kl * 32 + kk;
        a0 = fmaf(WoS[k + 0], Wv[(k + 0) * DIM + j], a0);
        a1 = fmaf(WoS[k + 1], Wv[(k + 1) * DIM + j], a1);
        a2 = fmaf(WoS[k + 2], Wv[(k + 2) * DIM + j], a2);
        a3 = fmaf(WoS[k + 3], Wv[(k + 3) * DIM + j], a3);
    }
    float acc = (a0 + a1) + (a2 + a3);
    acc += __shfl_xor_sync(0xffffffffu, acc, 1);
    acc += __shfl_xor_sync(0xffffffffu, acc, 2);
    if (kl == 0) g_Bc[i * DIM + j] = __float2half_rn(acc);

    int idx = b * 128 + tid;
    if (idx < N) g_mask[idx] = 0;
}

// ---------------------------------------------------------------------------
// Kernel 2: mask[tgt[e]] = 1, 4 edges per thread via int4.
// ---------------------------------------------------------------------------
__global__ void mask_kernel(const int* __restrict__ tgt, int E4) {
    int t = blockIdx.x * blockDim.x + threadIdx.x;
    if (t < E4) {
        int4 v = ((const int4*)tgt)[t];
        g_mask[v.x] = 1; g_mask[v.y] = 1; g_mask[v.z] = 1; g_mask[v.w] = 1;
    }
}

// ---------------------------------------------------------------------------
// Kernel 3: fp16 mma.sync GEMM, out = mask ? x @ Mc^T + bo : bo
// CTA: 64 rows x 128 cols, 8 warps (2x4), warp tile 32x32, mma m16n8k16.
// Direct-from-fragment epilogue (no smem staging).
// ---------------------------------------------------------------------------
#define ROWB   272                       // bytes per padded fp16 row
#define AS_OFF 0                         // 64*272  = 17408
#define BS_OFF 17408                     // 128*272 = 34816
#define BO_OFF 52224                     // 512 B
#define SMEM_SZ 52736

__global__ __launch_bounds__(256, 3) void gemm_kernel(const float* __restrict__ X,
                                                      const float* __restrict__ bo,
                                                      float* __restrict__ out, int Nn) {
    extern __shared__ unsigned char sm[];
    const int tid = threadIdx.x;
    const int warp = tid >> 5, lane = tid & 31;
    const int wm = warp & 1, wn = warp >> 1;       // 2x4 warp grid: 32-row x 32-col tiles
    const int gid = lane >> 2, tig = lane & 3;
    const uint32_t smb = smem_u32(sm);
    const int m0 = blockIdx.x * TM;

    // B: cp.async g_Bc (32KB hot in L2) into padded smem rows
#pragma unroll
    for (int i = tid; i < 2048; i += 256) {
        int r = i >> 4, seg = i & 15;
        cp_async16(smb + BS_OFF + r * ROWB + seg * 16, (const char*)g_Bc + i * 16);
    }
    asm volatile("cp.async.commit_group;" ::: "memory");
    if (tid < DIM) ((float*)(sm + BO_OFF))[tid] = bo[tid];

    // A: load x fp32 -> fp16, padded rows (8 float4 per thread)
#pragma unroll
    for (int it = 0; it < 8; ++it) {
        int f = tid + 256 * it;            // 0..2047
        int r = f >> 5;                    // row 0..63
        int c4 = (f & 31) << 2;            // col
        float4 v = make_float4(0.f, 0.f, 0.f, 0.f);
        int grow = m0 + r;
        if (grow < Nn) v = *(const float4*)&X[grow * DIM + c4];
        __half2 h01 = __float22half2_rn(make_float2(v.x, v.y));
        __half2 h23 = __float22half2_rn(make_float2(v.z, v.w));
        uint2 w;
        w.x = *(uint32_t*)&h01; w.y = *(uint32_t*)&h23;
        *(uint2*)(sm + AS_OFF + r * ROWB + c4 * 2) = w;
    }
    asm volatile("cp.async.wait_group 0;" ::: "memory");
    __syncthreads();

    // Mainloop: 8 k-steps of 16
    float acc[2][4][4];
#pragma unroll
    for (int mt = 0; mt < 2; ++mt)
#pragma unroll
        for (int nt = 0; nt < 4; ++nt)
#pragma unroll
            for (int q = 0; q < 4; ++q) acc[mt][nt][q] = 0.f;

    const uint32_t lrow = lane & 15;
    const uint32_t lk16 = (lane >> 4) * 16;
#pragma unroll
    for (int kk = 0; kk < 8; ++kk) {
        uint32_t af[2][4];
#pragma unroll
        for (int mt = 0; mt < 2; ++mt) {
            uint32_t a = smb + AS_OFF + (wm * 32 + mt * 16 + lrow) * ROWB + kk * 32 + lk16;
            ldsm4(af[mt][0], af[mt][1], af[mt][2], af[mt][3], a);
        }
        uint32_t bf[4][2];
#pragma unroll
        for (int np = 0; np < 2; ++np) {
            uint32_t a = smb + BS_OFF + (wn * 32 + np * 16 + lrow) * ROWB + kk * 32 + lk16;
            uint32_t r0, r1, r2, r3;
            ldsm4(r0, r1, r2, r3, a);
            bf[2 * np][0] = r0; bf[2 * np + 1][0] = r1;
            bf[2 * np][1] = r2; bf[2 * np + 1][1] = r3;
        }
#pragma unroll
        for (int mt = 0; mt < 2; ++mt)
#pragma unroll
            for (int nt = 0; nt < 4; ++nt)
                mma16816(acc[mt][nt], af[mt], bf[nt]);
    }

    // Epilogue: direct masked store from fragments (no staging).
    const float* boS = (const float*)(sm + BO_OFF);
#pragma unroll
    for (int mt = 0; mt < 2; ++mt) {
        int r0 = wm * 32 + mt * 16 + gid;
        int ga = m0 + r0, gb = ga + 8;
        bool va = ga < Nn, vb = gb < Nn;
        float ma = va ? (g_mask[ga] ? 1.0f : 0.0f) : 0.0f;
        float mb = vb ? (g_mask[gb] ? 1.0f : 0.0f) : 0.0f;
#pragma unroll
        for (int nt = 0; nt < 4; ++nt) {
            int col = wn * 32 + nt * 8 + 2 * tig;
            float b0 = boS[col], b1 = boS[col + 1];
            if (va)
                *(float2*)&out[ga * DIM + col] = make_float2(
                    fmaf(acc[mt][nt][0], ma, b0), fmaf(acc[mt][nt][1], ma, b1));
            if (vb)
                *(float2*)&out[gb * DIM + col] = make_float2(
                    fmaf(acc[mt][nt][2], mb, b0), fmaf(acc[mt][nt][3], mb, b1));
        }
    }
}

// ---------------------------------------------------------------------------
extern "C" void kernel_launch(void* const* d_in, const int* in_sizes, int n_in,
                              void* d_out, int out_size) {
    const float* x          = (const float*)d_in[0];
    const int*   edge_index = (const int*)d_in[1];
    const float* Wv         = (const float*)d_in[5];
    const float* Wo         = (const float*)d_in[7];
    const float* bo         = (const float*)d_in[8];
    float*       out        = (float*)d_out;

    const int N = in_sizes[0] / DIM;
    const int E = in_sizes[1] / 2;
    const int E4 = E / 4;

    cudaFuncSetAttribute(gemm_kernel, cudaFuncAttributeMaxDynamicSharedMemorySize,
                         SMEM_SZ);

    prep_kernel<<<512, 128>>>(Wo, Wv, N);
    mask_kernel<<<(E4 + 255) / 256, 256>>>(edge_index + E, E4);  // tgt = edge_index[1]
    gemm_kernel<<<(N + TM - 1) / TM, 256, SMEM_SZ>>>(x, bo, out, N);
}

// round 5
// speedup vs baseline: 1.1157x; 1.1157x over previous
#include <cuda_runtime.h>
#include <cuda_fp16.h>
#include <cstdint>

#define DIM 128
#define TM  64   // rows per gemm CTA

// ---------------------------------------------------------------------------
// Global scratch (no allocations allowed)
// ---------------------------------------------------------------------------
__device__ __align__(16) __half g_Bc[DIM * DIM];   // Mc = Wo@Wv, fp16, row-major [n][k]
// Invariant: all-zero at kernel_launch entry (zero-init + gemm epilogue cleanup).
__device__ unsigned char g_mask[131072];

__device__ __forceinline__ uint32_t smem_u32(const void* p) {
    uint32_t a;
    asm("{ .reg .u64 t; cvta.to.shared.u64 t, %1; cvt.u32.u64 %0, t; }" : "=r"(a) : "l"(p));
    return a;
}
__device__ __forceinline__ void ldsm4(uint32_t& r0, uint32_t& r1, uint32_t& r2,
                                      uint32_t& r3, uint32_t a) {
    asm volatile("ldmatrix.sync.aligned.m8n8.x4.shared.b16 {%0,%1,%2,%3}, [%4];"
                 : "=r"(r0), "=r"(r1), "=r"(r2), "=r"(r3) : "r"(a));
}
__device__ __forceinline__ void mma16816(float* c, const uint32_t* a, const uint32_t* b) {
    asm volatile(
        "mma.sync.aligned.m16n8k16.row.col.f32.f16.f16.f32 "
        "{%0,%1,%2,%3},{%4,%5,%6,%7},{%8,%9},{%0,%1,%2,%3};"
        : "+f"(c[0]), "+f"(c[1]), "+f"(c[2]), "+f"(c[3])
        : "r"(a[0]), "r"(a[1]), "r"(a[2]), "r"(a[3]), "r"(b[0]), "r"(b[1]));
}
__device__ __forceinline__ void cp_async16(uint32_t dst, const void* src) {
    asm volatile("cp.async.ca.shared.global [%0], [%1], 16;" :: "r"(dst), "l"(src)
                 : "memory");
}

// ---------------------------------------------------------------------------
// Kernel 1 (fused): blocks [0,128) compute Mc = Wo@Wv -> fp16;
//                   blocks [128, ...) scatter mask[tgt[e]] = 1.
// No mask clear needed: gemm epilogue re-zeroes consumed entries.
// ---------------------------------------------------------------------------
#define PREP_BLKS 128

__global__ __launch_bounds__(256) void prep_mask_kernel(const float* __restrict__ Wo,
                                                        const float* __restrict__ Wv,
                                                        const int* __restrict__ tgt,
                                                        int E) {
    const int b = blockIdx.x;
    const int t = threadIdx.x;
    if (b < PREP_BLKS) {
        // ---- prep: row i = b of Mc. 8-way k-split, float4 Wv loads (MLP=16).
        __shared__ float WoS[DIM];
        __shared__ float red[8 * 136];   // [kl][j], row stride 136 floats (16B mult)
        if (t < DIM) WoS[t] = Wo[b * DIM + t];
        __syncthreads();

        const int j4 = (t & 31) * 4;     // j column group (float4)
        const int kl = t >> 5;           // k-split lane 0..7 (16 k each)
        float a0 = 0.f, a1 = 0.f, a2 = 0.f, a3 = 0.f;
#pragma unroll
        for (int kk = 0; kk < 16; ++kk) {
            int k = kl * 16 + kk;
            float4 v = *(const float4*)&Wv[k * DIM + j4];
            float w = WoS[k];            // warp-uniform broadcast
            a0 = fmaf(w, v.x, a0);
            a1 = fmaf(w, v.y, a1);
            a2 = fmaf(w, v.z, a2);
            a3 = fmaf(w, v.w, a3);
        }
        *(float4*)&red[kl * 136 + j4] = make_float4(a0, a1, a2, a3);
        __syncthreads();
        if (t < DIM) {
            float s = 0.f;
#pragma unroll
            for (int kl2 = 0; kl2 < 8; ++kl2) s += red[kl2 * 136 + t];
            g_Bc[b * DIM + t] = __float2half_rn(s);
        }
    } else {
        // ---- mask scatter: 4 edges per thread via int4.
        const int E4 = E >> 2;
        int e4 = (b - PREP_BLKS) * 256 + t;
        if (e4 < E4) {
            int4 v = ((const int4*)tgt)[e4];
            g_mask[v.x] = 1; g_mask[v.y] = 1; g_mask[v.z] = 1; g_mask[v.w] = 1;
        }
        if (b == PREP_BLKS && t < (E & 3))   // tail
            g_mask[tgt[E4 * 4 + t]] = 1;
    }
}

// ---------------------------------------------------------------------------
// Kernel 2: fp16 mma.sync GEMM, out = mask ? x @ Mc^T + bo : bo
// CTA: 64 rows x 128 cols, 8 warps (2x4), warp tile 32x32, mma m16n8k16.
// Direct-from-fragment epilogue; clears its mask slice afterwards.
// ---------------------------------------------------------------------------
#define ROWB   272                       // bytes per padded fp16 row
#define AS_OFF 0                         // 64*272  = 17408
#define BS_OFF 17408                     // 128*272 = 34816
#define BO_OFF 52224                     // 512 B
#define SMEM_SZ 52736

__global__ __launch_bounds__(256, 3) void gemm_kernel(const float* __restrict__ X,
                                                      const float* __restrict__ bo,
                                                      float* __restrict__ out, int Nn) {
    extern __shared__ unsigned char sm[];
    const int tid = threadIdx.x;
    const int warp = tid >> 5, lane = tid & 31;
    const int wm = warp & 1, wn = warp >> 1;       // 2x4 warp grid: 32-row x 32-col tiles
    const int gid = lane >> 2, tig = lane & 3;
    const uint32_t smb = smem_u32(sm);
    const int m0 = blockIdx.x * TM;

    // B: cp.async g_Bc (32KB hot in L2) into padded smem rows
#pragma unroll
    for (int i = tid; i < 2048; i += 256) {
        int r = i >> 4, seg = i & 15;
        cp_async16(smb + BS_OFF + r * ROWB + seg * 16, (const char*)g_Bc + i * 16);
    }
    asm volatile("cp.async.commit_group;" ::: "memory");
    if (tid < DIM) ((float*)(sm + BO_OFF))[tid] = bo[tid];

    // A: load x fp32 -> fp16, padded rows (8 float4 per thread)
#pragma unroll
    for (int it = 0; it < 8; ++it) {
        int f = tid + 256 * it;            // 0..2047
        int r = f >> 5;                    // row 0..63
        int c4 = (f & 31) << 2;            // col
        float4 v = make_float4(0.f, 0.f, 0.f, 0.f);
        int grow = m0 + r;
        if (grow < Nn) v = *(const float4*)&X[grow * DIM + c4];
        __half2 h01 = __float22half2_rn(make_float2(v.x, v.y));
        __half2 h23 = __float22half2_rn(make_float2(v.z, v.w));
        uint2 w;
        w.x = *(uint32_t*)&h01; w.y = *(uint32_t*)&h23;
        *(uint2*)(sm + AS_OFF + r * ROWB + c4 * 2) = w;
    }
    asm volatile("cp.async.wait_group 0;" ::: "memory");
    __syncthreads();

    // Mainloop: 8 k-steps of 16
    float acc[2][4][4];
#pragma unroll
    for (int mt = 0; mt < 2; ++mt)
#pragma unroll
        for (int nt = 0; nt < 4; ++nt)
#pragma unroll
            for (int q = 0; q < 4; ++q) acc[mt][nt][q] = 0.f;

    const uint32_t lrow = lane & 15;
    const uint32_t lk16 = (lane >> 4) * 16;
#pragma unroll
    for (int kk = 0; kk < 8; ++kk) {
        uint32_t af[2][4];
#pragma unroll
        for (int mt = 0; mt < 2; ++mt) {
            uint32_t a = smb + AS_OFF + (wm * 32 + mt * 16 + lrow) * ROWB + kk * 32 + lk16;
            ldsm4(af[mt][0], af[mt][1], af[mt][2], af[mt][3], a);
        }
        uint32_t bf[4][2];
#pragma unroll
        for (int np = 0; np < 2; ++np) {
            uint32_t a = smb + BS_OFF + (wn * 32 + np * 16 + lrow) * ROWB + kk * 32 + lk16;
            uint32_t r0, r1, r2, r3;
            ldsm4(r0, r1, r2, r3, a);
            bf[2 * np][0] = r0; bf[2 * np + 1][0] = r1;
            bf[2 * np][1] = r2; bf[2 * np + 1][1] = r3;
        }
#pragma unroll
        for (int mt = 0; mt < 2; ++mt)
#pragma unroll
            for (int nt = 0; nt < 4; ++nt)
                mma16816(acc[mt][nt], af[mt], bf[nt]);
    }

    // Epilogue: direct masked store from fragments (no staging).
    const float* boS = (const float*)(sm + BO_OFF);
#pragma unroll
    for (int mt = 0; mt < 2; ++mt) {
        int r0 = wm * 32 + mt * 16 + gid;
        int ga = m0 + r0, gb = ga + 8;
        bool va = ga < Nn, vb = gb < Nn;
        float ma = va ? (g_mask[ga] ? 1.0f : 0.0f) : 0.0f;
        float mb = vb ? (g_mask[gb] ? 1.0f : 0.0f) : 0.0f;
#pragma unroll
        for (int nt = 0; nt < 4; ++nt) {
            int col = wn * 32 + nt * 8 + 2 * tig;
            float b0 = boS[col], b1 = boS[col + 1];
            if (va)
                *(float2*)&out[ga * DIM + col] = make_float2(
                    fmaf(acc[mt][nt][0], ma, b0), fmaf(acc[mt][nt][1], ma, b1));
            if (vb)
                *(float2*)&out[gb * DIM + col] = make_float2(
                    fmaf(acc[mt][nt][2], mb, b0), fmaf(acc[mt][nt][3], mb, b1));
        }
    }

    // Re-zero this CTA's mask slice (after ALL warps have read it) so the
    // next kernel_launch starts from an all-zero mask without a clear pass.
    __syncthreads();
    if (tid < TM) {
        int grow = m0 + tid;
        if (grow < Nn) g_mask[grow] = 0;
    }
}

// ---------------------------------------------------------------------------
extern "C" void kernel_launch(void* const* d_in, const int* in_sizes, int n_in,
                              void* d_out, int out_size) {
    const float* x          = (const float*)d_in[0];
    const int*   edge_index = (const int*)d_in[1];
    const float* Wv         = (const float*)d_in[5];
    const float* Wo         = (const float*)d_in[7];
    const float* bo         = (const float*)d_in[8];
    float*       out        = (float*)d_out;

    const int N = in_sizes[0] / DIM;
    const int E = in_sizes[1] / 2;
    const int mask_blks = (E / 4 + 255) / 256 + 1;

    cudaFuncSetAttribute(gemm_kernel, cudaFuncAttributeMaxDynamicSharedMemorySize,
                         SMEM_SZ);

    prep_mask_kernel<<<PREP_BLKS + mask_blks, 256>>>(Wo, Wv, edge_index + E, E);
    gemm_kernel<<<(N + TM - 1) / TM, 256, SMEM_SZ>>>(x, bo, out, N);
}

// round 7
// speedup vs baseline: 1.3068x; 1.1713x over previous
#include <cuda_runtime.h>
#include <cuda_fp16.h>
#include <cstdint>

#define DIM 128
#define TM  64        // rows per gemm CTA
#define SCAT 64       // scatter CTAs prepended to gemm grid

// ---------------------------------------------------------------------------
// Global scratch (no allocations allowed)
// ---------------------------------------------------------------------------
__device__ __align__(16) __half g_Bc[DIM * DIM];   // Mc = Wo@Wv, fp16, [n][k]
// Bitmap of nodes with >=1 incoming edge. Invariant: all-zero at every
// kernel_launch entry (zero-init + fixup cleanup).
__device__ uint32_t g_maskbits[4096];

__device__ __forceinline__ uint32_t smem_u32(const void* p) {
    uint32_t a;
    asm("{ .reg .u64 t; cvta.to.shared.u64 t, %1; cvt.u32.u64 %0, t; }" : "=r"(a) : "l"(p));
    return a;
}
__device__ __forceinline__ void ldsm4(uint32_t& r0, uint32_t& r1, uint32_t& r2,
                                      uint32_t& r3, uint32_t a) {
    asm volatile("ldmatrix.sync.aligned.m8n8.x4.shared.b16 {%0,%1,%2,%3}, [%4];"
                 : "=r"(r0), "=r"(r1), "=r"(r2), "=r"(r3) : "r"(a));
}
__device__ __forceinline__ void mma16816(float* c, const uint32_t* a, const uint32_t* b) {
    asm volatile(
        "mma.sync.aligned.m16n8k16.row.col.f32.f16.f16.f32 "
        "{%0,%1,%2,%3},{%4,%5,%6,%7},{%8,%9},{%0,%1,%2,%3};"
        : "+f"(c[0]), "+f"(c[1]), "+f"(c[2]), "+f"(c[3])
        : "r"(a[0]), "r"(a[1]), "r"(a[2]), "r"(a[3]), "r"(b[0]), "r"(b[1]));
}
__device__ __forceinline__ void cp_async16(uint32_t dst, const void* src) {
    asm volatile("cp.async.ca.shared.global [%0], [%1], 16;" :: "r"(dst), "l"(src)
                 : "memory");
}

// ---------------------------------------------------------------------------
// prep: Mc = Wo @ Wv -> fp16.  128 blocks x 256 thr, 8-way k-split.
// ---------------------------------------------------------------------------
__global__ __launch_bounds__(256) void prep_kernel(const float* __restrict__ Wo,
                                                   const float* __restrict__ Wv) {
    __shared__ float WoS[DIM];
    __shared__ float red[8 * 136];
    const int b = blockIdx.x;
    const int t = threadIdx.x;
    if (t < DIM) WoS[t] = Wo[b * DIM + t];
    __syncthreads();

    const int j4 = (t & 31) * 4;
    const int kl = t >> 5;
    float a0 = 0.f, a1 = 0.f, a2 = 0.f, a3 = 0.f;
#pragma unroll
    for (int kk = 0; kk < 16; ++kk) {
        int k = kl * 16 + kk;
        float4 v = *(const float4*)&Wv[k * DIM + j4];
        float w = WoS[k];
        a0 = fmaf(w, v.x, a0);
        a1 = fmaf(w, v.y, a1);
        a2 = fmaf(w, v.z, a2);
        a3 = fmaf(w, v.w, a3);
    }
    *(float4*)&red[kl * 136 + j4] = make_float4(a0, a1, a2, a3);
    __syncthreads();
    if (t < DIM) {
        float s = 0.f;
#pragma unroll
        for (int kl2 = 0; kl2 < 8; ++kl2) s += red[kl2 * 136 + t];
        g_Bc[b * DIM + t] = __float2half_rn(s);
    }
}

// ---------------------------------------------------------------------------
// Fused kernel: blocks [0, SCAT) scatter edge bitmap (smem-private, merged
// via coalesced atomicOr); blocks [SCAT, ...) do the GEMM. The two groups are
// independent and overlap within one launch.
// gemm: out = x @ Mc^T + bo (unconditional; zero-degree rows fixed up after).
// ---------------------------------------------------------------------------
#define ROWB   272
#define AS_OFF 0
#define BS_OFF 17408
#define BO_OFF 52224
#define SMEM_SZ 52736

__global__ __launch_bounds__(256, 3) void gemm_scat_kernel(
    const float* __restrict__ X, const float* __restrict__ bo,
    const int* __restrict__ tgt, float* __restrict__ out, int Nn, int E) {
    extern __shared__ unsigned char sm[];
    const int tid = threadIdx.x;

    if (blockIdx.x < SCAT) {
        // ---------------- scatter path ----------------
        uint32_t* bm = (uint32_t*)sm;
        const int nwords = (Nn + 31) >> 5;
        for (int i = tid; i < nwords; i += 256) bm[i] = 0;
        __syncthreads();

        const int E4 = E >> 2;
        const int4* tgt4 = (const int4*)tgt;
        for (int i = blockIdx.x * 256 + tid; i < E4; i += SCAT * 256) {
            int4 v = tgt4[i];
            atomicOr(&bm[v.x >> 5], 1u << (v.x & 31));
            atomicOr(&bm[v.y >> 5], 1u << (v.y & 31));
            atomicOr(&bm[v.z >> 5], 1u << (v.z & 31));
            atomicOr(&bm[v.w >> 5], 1u << (v.w & 31));
        }
        if (blockIdx.x == 0 && tid < (E & 3)) {   // tail (<4 edges)
            int n = tgt[E4 * 4 + tid];
            atomicOr(&g_maskbits[n >> 5], 1u << (n & 31));
        }
        __syncthreads();
        for (int i = tid; i < nwords; i += 256) {
            uint32_t w = bm[i];
            if (w) atomicOr(&g_maskbits[i], w);
        }
        return;
    }

    // ---------------- gemm path ----------------
    const int warp = tid >> 5, lane = tid & 31;
    const int wm = warp & 1, wn = warp >> 1;
    const int gid = lane >> 2, tig = lane & 3;
    const uint32_t smb = smem_u32(sm);
    const int m0 = (blockIdx.x - SCAT) * TM;

#pragma unroll
    for (int i = tid; i < 2048; i += 256) {
        int r = i >> 4, seg = i & 15;
        cp_async16(smb + BS_OFF + r * ROWB + seg * 16, (const char*)g_Bc + i * 16);
    }
    asm volatile("cp.async.commit_group;" ::: "memory");
    if (tid < DIM) ((float*)(sm + BO_OFF))[tid] = bo[tid];

#pragma unroll
    for (int it = 0; it < 8; ++it) {
        int f = tid + 256 * it;
        int r = f >> 5;
        int c4 = (f & 31) << 2;
        float4 v = make_float4(0.f, 0.f, 0.f, 0.f);
        int grow = m0 + r;
        if (grow < Nn) v = *(const float4*)&X[grow * DIM + c4];
        __half2 h01 = __float22half2_rn(make_float2(v.x, v.y));
        __half2 h23 = __float22half2_rn(make_float2(v.z, v.w));
        uint2 w;
        w.x = *(uint32_t*)&h01; w.y = *(uint32_t*)&h23;
        *(uint2*)(sm + AS_OFF + r * ROWB + c4 * 2) = w;
    }
    asm volatile("cp.async.wait_group 0;" ::: "memory");
    __syncthreads();

    float acc[2][4][4];
#pragma unroll
    for (int mt = 0; mt < 2; ++mt)
#pragma unroll
        for (int nt = 0; nt < 4; ++nt)
#pragma unroll
            for (int q = 0; q < 4; ++q) acc[mt][nt][q] = 0.f;

    const uint32_t lrow = lane & 15;
    const uint32_t lk16 = (lane >> 4) * 16;
#pragma unroll
    for (int kk = 0; kk < 8; ++kk) {
        uint32_t af[2][4];
#pragma unroll
        for (int mt = 0; mt < 2; ++mt) {
            uint32_t a = smb + AS_OFF + (wm * 32 + mt * 16 + lrow) * ROWB + kk * 32 + lk16;
            ldsm4(af[mt][0], af[mt][1], af[mt][2], af[mt][3], a);
        }
        uint32_t bf[4][2];
#pragma unroll
        for (int np = 0; np < 2; ++np) {
            uint32_t a = smb + BS_OFF + (wn * 32 + np * 16 + lrow) * ROWB + kk * 32 + lk16;
            uint32_t r0, r1, r2, r3;
            ldsm4(r0, r1, r2, r3, a);
            bf[2 * np][0] = r0; bf[2 * np + 1][0] = r1;
            bf[2 * np][1] = r2; bf[2 * np + 1][1] = r3;
        }
#pragma unroll
        for (int mt = 0; mt < 2; ++mt)
#pragma unroll
            for (int nt = 0; nt < 4; ++nt)
                mma16816(acc[mt][nt], af[mt], bf[nt]);
    }

    const float* boS = (const float*)(sm + BO_OFF);
#pragma unroll
    for (int mt = 0; mt < 2; ++mt) {
        int r0 = wm * 32 + mt * 16 + gid;
        int ga = m0 + r0, gb = ga + 8;
#pragma unroll
        for (int nt = 0; nt < 4; ++nt) {
            int col = wn * 32 + nt * 8 + 2 * tig;
            float b0 = boS[col], b1 = boS[col + 1];
            if (ga < Nn)
                *(float2*)&out[ga * DIM + col] = make_float2(
                    acc[mt][nt][0] + b0, acc[mt][nt][1] + b1);
            if (gb < Nn)
                *(float2*)&out[gb * DIM + col] = make_float2(
                    acc[mt][nt][2] + b0, acc[mt][nt][3] + b1);
        }
    }
}

// ---------------------------------------------------------------------------
// fixup: rows with no incoming edge -> bo; re-zero bitmap for next replay.
// 256-thread blocks: each warp covers 32 consecutive nodes = exactly 1 word.
// ---------------------------------------------------------------------------
__global__ __launch_bounds__(256) void fixup_kernel(const float* __restrict__ bo,
                                                    float* __restrict__ out, int Nn) {
    int n = blockIdx.x * blockDim.x + threadIdx.x;
    uint32_t w = 0;
    if (n < Nn) w = g_maskbits[n >> 5];
    __syncwarp();
    if (n < Nn && (n & 31) == 0) g_maskbits[n >> 5] = 0;   // clear after reads
    if (n < Nn && !((w >> (n & 31)) & 1u)) {
        float4* dst = (float4*)&out[n * DIM];
        const float4* src = (const float4*)bo;
#pragma unroll
        for (int c = 0; c < 32; ++c) dst[c] = src[c];
    }
}

// ---------------------------------------------------------------------------
extern "C" void kernel_launch(void* const* d_in, const int* in_sizes, int n_in,
                              void* d_out, int out_size) {
    const float* x          = (const float*)d_in[0];
    const int*   edge_index = (const int*)d_in[1];
    const float* Wv         = (const float*)d_in[5];
    const float* Wo         = (const float*)d_in[7];
    const float* bo         = (const float*)d_in[8];
    float*       out        = (float*)d_out;

    const int N = in_sizes[0] / DIM;
    const int E = in_sizes[1] / 2;
    const int* tgt = edge_index + E;
    const int gemm_blks = (N + TM - 1) / TM;

    cudaFuncSetAttribute(gemm_scat_kernel, cudaFuncAttributeMaxDynamicSharedMemorySize,
                         SMEM_SZ);

    prep_kernel<<<128, 256>>>(Wo, Wv);
    gemm_scat_kernel<<<SCAT + gemm_blks, 256, SMEM_SZ>>>(x, bo, tgt, out, N, E);
    fixup_kernel<<<(N + 255) / 256, 256>>>(bo, out, N);
}

// round 8
// speedup vs baseline: 1.8178x; 1.3910x over previous
#include <cuda_runtime.h>
#include <cuda_fp16.h>
#include <cstdint>

#define DIM 128
#define TM  64        // rows per gemm CTA
#define PREP 128      // prep CTAs (compute Mc)
#define SCAT 64       // scatter CTAs

// ---------------------------------------------------------------------------
// Global scratch (no allocations allowed)
// ---------------------------------------------------------------------------
__device__ __align__(16) __half g_Bc[DIM * DIM];   // Mc = Wo@Wv, fp16, [n][k]
// Bitmap of nodes with >=1 incoming edge. Invariant: all-zero at every
// kernel_launch entry (zero-init + fixup cleanup).
__device__ uint32_t g_maskbits[4096];
__device__ uint32_t g_done;   // prep completion counter; reset by fixup

__device__ __forceinline__ uint32_t smem_u32(const void* p) {
    uint32_t a;
    asm("{ .reg .u64 t; cvta.to.shared.u64 t, %1; cvt.u32.u64 %0, t; }" : "=r"(a) : "l"(p));
    return a;
}
__device__ __forceinline__ uint32_t ld_acquire(const uint32_t* p) {
    uint32_t v;
    asm volatile("ld.acquire.gpu.u32 %0, [%1];" : "=r"(v) : "l"(p) : "memory");
    return v;
}
__device__ __forceinline__ void ldsm4(uint32_t& r0, uint32_t& r1, uint32_t& r2,
                                      uint32_t& r3, uint32_t a) {
    asm volatile("ldmatrix.sync.aligned.m8n8.x4.shared.b16 {%0,%1,%2,%3}, [%4];"
                 : "=r"(r0), "=r"(r1), "=r"(r2), "=r"(r3) : "r"(a));
}
__device__ __forceinline__ void mma16816(float* c, const uint32_t* a, const uint32_t* b) {
    asm volatile(
        "mma.sync.aligned.m16n8k16.row.col.f32.f16.f16.f32 "
        "{%0,%1,%2,%3},{%4,%5,%6,%7},{%8,%9},{%0,%1,%2,%3};"
        : "+f"(c[0]), "+f"(c[1]), "+f"(c[2]), "+f"(c[3])
        : "r"(a[0]), "r"(a[1]), "r"(a[2]), "r"(a[3]), "r"(b[0]), "r"(b[1]));
}
__device__ __forceinline__ void cp_async16(uint32_t dst, const void* src) {
    asm volatile("cp.async.ca.shared.global [%0], [%1], 16;" :: "r"(dst), "l"(src)
                 : "memory");
}

// ---------------------------------------------------------------------------
// Fused kernel:
//   blocks [0, PREP)           : Mc = Wo@Wv row -> g_Bc, then signal g_done
//   blocks [PREP, PREP+SCAT)   : edge bitmap scatter (smem-private + atomicOr)
//   blocks [PREP+SCAT, ...)    : GEMM out = x @ Mc^T + bo (unconditional);
//                                A-load first, spin on g_done, then B + MMA.
// ---------------------------------------------------------------------------
#define ROWB   272
#define AS_OFF 0
#define BS_OFF 17408
#define BO_OFF 52224
#define SMEM_SZ 52736

__global__ __launch_bounds__(256, 3) void fused_kernel(
    const float* __restrict__ X, const float* __restrict__ Wo,
    const float* __restrict__ Wv, const float* __restrict__ bo,
    const int* __restrict__ tgt, float* __restrict__ out, int Nn, int E) {
    extern __shared__ unsigned char sm[];
    const int tid = threadIdx.x;

    if (blockIdx.x < PREP) {
        // ---------------- prep path: one row of Mc ----------------
        float* WoS = (float*)sm;              // [128]
        float* red = (float*)sm + 128;        // [8*136]
        const int b = blockIdx.x;
        if (tid < DIM) WoS[tid] = Wo[b * DIM + tid];
        __syncthreads();

        const int j4 = (tid & 31) * 4;
        const int kl = tid >> 5;
        float a0 = 0.f, a1 = 0.f, a2 = 0.f, a3 = 0.f;
#pragma unroll
        for (int kk = 0; kk < 16; ++kk) {
            int k = kl * 16 + kk;
            float4 v = *(const float4*)&Wv[k * DIM + j4];
            float w = WoS[k];
            a0 = fmaf(w, v.x, a0);
            a1 = fmaf(w, v.y, a1);
            a2 = fmaf(w, v.z, a2);
            a3 = fmaf(w, v.w, a3);
        }
        *(float4*)&red[kl * 136 + j4] = make_float4(a0, a1, a2, a3);
        __syncthreads();
        if (tid < DIM) {
            float s = 0.f;
#pragma unroll
            for (int kl2 = 0; kl2 < 8; ++kl2) s += red[kl2 * 136 + tid];
            g_Bc[b * DIM + tid] = __float2half_rn(s);
        }
        __syncthreads();
        if (tid == 0) {
            __threadfence();
            atomicAdd(&g_done, 1u);
        }
        return;
    }

    if (blockIdx.x < PREP + SCAT) {
        // ---------------- scatter path ----------------
        uint32_t* bm = (uint32_t*)sm;
        const int bs = blockIdx.x - PREP;
        const int nwords = (Nn + 31) >> 5;
        for (int i = tid; i < nwords; i += 256) bm[i] = 0;
        __syncthreads();

        const int E4 = E >> 2;
        const int4* tgt4 = (const int4*)tgt;
        for (int i = bs * 256 + tid; i < E4; i += SCAT * 256) {
            int4 v = tgt4[i];
            atomicOr(&bm[v.x >> 5], 1u << (v.x & 31));
            atomicOr(&bm[v.y >> 5], 1u << (v.y & 31));
            atomicOr(&bm[v.z >> 5], 1u << (v.z & 31));
            atomicOr(&bm[v.w >> 5], 1u << (v.w & 31));
        }
        if (bs == 0 && tid < (E & 3)) {   // tail (<4 edges)
            int n = tgt[E4 * 4 + tid];
            atomicOr(&g_maskbits[n >> 5], 1u << (n & 31));
        }
        __syncthreads();
        for (int i = tid; i < nwords; i += 256) {
            uint32_t w = bm[i];
            if (w) atomicOr(&g_maskbits[i], w);
        }
        return;
    }

    // ---------------- gemm path ----------------
    const int warp = tid >> 5, lane = tid & 31;
    const int wm = warp & 1, wn = warp >> 1;
    const int gid = lane >> 2, tig = lane & 3;
    const uint32_t smb = smem_u32(sm);
    const int m0 = (blockIdx.x - PREP - SCAT) * TM;

    // A first (DRAM-heavy, independent of prep): x fp32 -> fp16 into padded rows
#pragma unroll
    for (int it = 0; it < 8; ++it) {
        int f = tid + 256 * it;
        int r = f >> 5;
        int c4 = (f & 31) << 2;
        float4 v = make_float4(0.f, 0.f, 0.f, 0.f);
        int grow = m0 + r;
        if (grow < Nn) v = *(const float4*)&X[grow * DIM + c4];
        __half2 h01 = __float22half2_rn(make_float2(v.x, v.y));
        __half2 h23 = __float22half2_rn(make_float2(v.z, v.w));
        uint2 w;
        w.x = *(uint32_t*)&h01; w.y = *(uint32_t*)&h23;
        *(uint2*)(sm + AS_OFF + r * ROWB + c4 * 2) = w;
    }
    if (tid < DIM) ((float*)(sm + BO_OFF))[tid] = bo[tid];

    // Wait for prep completion (one spinner, others park at the barrier).
    if (tid == 0) {
        while (ld_acquire(&g_done) < PREP) { }
    }
    __syncthreads();   // covers A-tile visibility + flag

    // B: cp.async g_Bc (now ready, hot in L2) into padded smem rows
#pragma unroll
    for (int i = tid; i < 2048; i += 256) {
        int r = i >> 4, seg = i & 15;
        cp_async16(smb + BS_OFF + r * ROWB + seg * 16, (const char*)g_Bc + i * 16);
    }
    asm volatile("cp.async.commit_group;" ::: "memory");
    asm volatile("cp.async.wait_group 0;" ::: "memory");
    __syncthreads();

    float acc[2][4][4];
#pragma unroll
    for (int mt = 0; mt < 2; ++mt)
#pragma unroll
        for (int nt = 0; nt < 4; ++nt)
#pragma unroll
            for (int q = 0; q < 4; ++q) acc[mt][nt][q] = 0.f;

    const uint32_t lrow = lane & 15;
    const uint32_t lk16 = (lane >> 4) * 16;
#pragma unroll
    for (int kk = 0; kk < 8; ++kk) {
        uint32_t af[2][4];
#pragma unroll
        for (int mt = 0; mt < 2; ++mt) {
            uint32_t a = smb + AS_OFF + (wm * 32 + mt * 16 + lrow) * ROWB + kk * 32 + lk16;
            ldsm4(af[mt][0], af[mt][1], af[mt][2], af[mt][3], a);
        }
        uint32_t bf[4][2];
#pragma unroll
        for (int np = 0; np < 2; ++np) {
            uint32_t a = smb + BS_OFF + (wn * 32 + np * 16 + lrow) * ROWB + kk * 32 + lk16;
            uint32_t r0, r1, r2, r3;
            ldsm4(r0, r1, r2, r3, a);
            bf[2 * np][0] = r0; bf[2 * np + 1][0] = r1;
            bf[2 * np][1] = r2; bf[2 * np + 1][1] = r3;
        }
#pragma unroll
        for (int mt = 0; mt < 2; ++mt)
#pragma unroll
            for (int nt = 0; nt < 4; ++nt)
                mma16816(acc[mt][nt], af[mt], bf[nt]);
    }

    const float* boS = (const float*)(sm + BO_OFF);
#pragma unroll
    for (int mt = 0; mt < 2; ++mt) {
        int r0 = wm * 32 + mt * 16 + gid;
        int ga = m0 + r0, gb = ga + 8;
#pragma unroll
        for (int nt = 0; nt < 4; ++nt) {
            int col = wn * 32 + nt * 8 + 2 * tig;
            float b0 = boS[col], b1 = boS[col + 1];
            if (ga < Nn)
                *(float2*)&out[ga * DIM + col] = make_float2(
                    acc[mt][nt][0] + b0, acc[mt][nt][1] + b1);
            if (gb < Nn)
                *(float2*)&out[gb * DIM + col] = make_float2(
                    acc[mt][nt][2] + b0, acc[mt][nt][3] + b1);
        }
    }
}

// ---------------------------------------------------------------------------
// fixup: rows with no incoming edge -> bo; reset bitmap + g_done for replay.
// ---------------------------------------------------------------------------
__global__ __launch_bounds__(256) void fixup_kernel(const float* __restrict__ bo,
                                                    float* __restrict__ out, int Nn) {
    int n = blockIdx.x * blockDim.x + threadIdx.x;
    if (n == 0) g_done = 0;
    uint32_t w = 0;
    if (n < Nn) w = g_maskbits[n >> 5];
    __syncwarp();
    if (n < Nn && (n & 31) == 0) g_maskbits[n >> 5] = 0;   // clear after reads
    if (n < Nn && !((w >> (n & 31)) & 1u)) {
        float4* dst = (float4*)&out[n * DIM];
        const float4* src = (const float4*)bo;
#pragma unroll
        for (int c = 0; c < 32; ++c) dst[c] = src[c];
    }
}

// ---------------------------------------------------------------------------
extern "C" void kernel_launch(void* const* d_in, const int* in_sizes, int n_in,
                              void* d_out, int out_size) {
    const float* x          = (const float*)d_in[0];
    const int*   edge_index = (const int*)d_in[1];
    const float* Wv         = (const float*)d_in[5];
    const float* Wo         = (const float*)d_in[7];
    const float* bo         = (const float*)d_in[8];
    float*       out        = (float*)d_out;

    const int N = in_sizes[0] / DIM;
    const int E = in_sizes[1] / 2;
    const int* tgt = edge_index + E;
    const int gemm_blks = (N + TM - 1) / TM;

    cudaFuncSetAttribute(fused_kernel, cudaFuncAttributeMaxDynamicSharedMemorySize,
                         SMEM_SZ);

    fused_kernel<<<PREP + SCAT + gemm_blks, 256, SMEM_SZ>>>(x, Wo, Wv, bo, tgt,
                                                            out, N, E);
    fixup_kernel<<<(N + 255) / 256, 256>>>(bo, out, N);
}